// round 14
// baseline (speedup 1.0000x reference)
#include <cuda_runtime.h>

#define NN 50000
#define NE 800000
#define NG 64
#define FD 128
#define NEG_SLOPE 0.2f

// ---------------- device scratch (allocation-free rule: __device__ globals) ---
__device__ float g_hA[(size_t)NN * FD];   // current features / aggregation target
__device__ float g_h2[(size_t)NN * FD];   // transformed features h @ Wc
__device__ float g_as[NN];                // alpha_src per node
__device__ float g_ad[NN];                // alpha_dst per node
__device__ float g_emax[NN];              // segment max
__device__ float g_den[NN];               // segment softmax denominator
__device__ float g_pool[NG * FD];         // pooled sums
__device__ float g_cnt[NG];               // node counts per graph

__device__ __forceinline__ float lrelu(float x) { return x > 0.f ? x : NEG_SLOPE * x; }

__device__ __forceinline__ void atomicMaxF(float* addr, float val) {
    // monotone-toward-max under both ops; correct for mixed signs
    if (val >= 0.f) atomicMax((int*)addr, __float_as_int(val));
    else            atomicMin((unsigned int*)addr, __float_as_uint(val));
}

// ---------------- GEMM: C[nrows,128] = f(A)[nrows,128] @ B[128,128] ----------
// f(A) = optional (A + in_bias) then relu (fuses the post-aggregation bias+relu
// of the previous GAT layer into the next layer's GEMM load).
__global__ __launch_bounds__(128) void gemm_kernel(
    const float* __restrict__ A, const float* __restrict__ B,
    const float* __restrict__ in_bias, int in_relu,
    const float* __restrict__ out_bias, int out_relu,
    float* __restrict__ C, int nrows)
{
    __shared__ __align__(16) float As[64][33];
    __shared__ __align__(16) float Bs[32][132];

    const int tid  = threadIdx.x;
    const int row0 = blockIdx.x * 64;
    const int tr   = tid >> 4;   // 0..7  -> rows tr*8 .. tr*8+7
    const int tc   = tid & 15;   // 0..15 -> cols tc*8 .. tc*8+7

    float acc[8][8] = {};

    for (int kt = 0; kt < 128; kt += 32) {
        // load A tile 64x32 (with optional input transform)
        #pragma unroll
        for (int i = tid; i < 64 * 32; i += 128) {
            int rr = i >> 5, kk = i & 31;
            int row = row0 + rr;
            float v = 0.f;
            if (row < nrows) {
                v = A[(size_t)row * FD + kt + kk];
                if (in_bias) v += in_bias[kt + kk];
                if (in_relu) v = fmaxf(v, 0.f);
            }
            As[rr][kk] = v;
        }
        // load B tile 32x128 (coalesced)
        #pragma unroll
        for (int i = tid; i < 32 * 128; i += 128) {
            int kk = i >> 7, cc = i & 127;
            Bs[kk][cc] = B[(size_t)(kt + kk) * FD + cc];
        }
        __syncthreads();

        #pragma unroll
        for (int k = 0; k < 32; k++) {
            float a[8];
            #pragma unroll
            for (int i = 0; i < 8; i++) a[i] = As[tr * 8 + i][k];
            float4 b0 = *(const float4*)&Bs[k][tc * 8];
            float4 b1 = *(const float4*)&Bs[k][tc * 8 + 4];
            float b[8] = {b0.x, b0.y, b0.z, b0.w, b1.x, b1.y, b1.z, b1.w};
            #pragma unroll
            for (int i = 0; i < 8; i++)
                #pragma unroll
                for (int j = 0; j < 8; j++)
                    acc[i][j] += a[i] * b[j];
        }
        __syncthreads();
    }

    #pragma unroll
    for (int i = 0; i < 8; i++) {
        int row = row0 + tr * 8 + i;
        if (row >= nrows) break;
        #pragma unroll
        for (int j = 0; j < 8; j++) {
            int c = tc * 8 + j;
            float v = acc[i][j];
            if (out_bias) v += out_bias[c];
            if (out_relu) v = fmaxf(v, 0.f);
            C[(size_t)row * FD + c] = v;
        }
    }
}

// ---------------- per-node alpha dots + self-loop init of e_max --------------
__global__ void node_alpha_kernel(const float* __restrict__ asrc,
                                  const float* __restrict__ adst)
{
    int idx  = blockIdx.x * blockDim.x + threadIdx.x;
    int n    = idx >> 5;
    int lane = idx & 31;
    if (n >= NN) return;
    float4 h = ((const float4*)(g_h2 + (size_t)n * FD))[lane];
    float4 s = ((const float4*)asrc)[lane];
    float4 d = ((const float4*)adst)[lane];
    float ss = h.x * s.x + h.y * s.y + h.z * s.z + h.w * s.w;
    float dd = h.x * d.x + h.y * d.y + h.z * d.z + h.w * d.w;
    #pragma unroll
    for (int o = 16; o > 0; o >>= 1) {
        ss += __shfl_down_sync(0xffffffffu, ss, o);
        dd += __shfl_down_sync(0xffffffffu, dd, o);
    }
    if (lane == 0) {
        g_as[n]   = ss;
        g_ad[n]   = dd;
        g_emax[n] = lrelu(ss + dd);   // self-loop edge initializes segment max
    }
}

__global__ void edge_max_kernel(const int* __restrict__ ei)
{
    int e = blockIdx.x * blockDim.x + threadIdx.x;
    if (e >= NE) return;
    int s = ei[e], d = ei[NE + e];
    atomicMaxF(&g_emax[d], lrelu(g_as[s] + g_ad[d]));
}

__global__ void node_denom_kernel()
{
    int n = blockIdx.x * blockDim.x + threadIdx.x;
    if (n >= NN) return;
    // self-loop contribution initializes the denominator
    g_den[n] = expf(lrelu(g_as[n] + g_ad[n]) - g_emax[n]);
}

__global__ void edge_sum_kernel(const int* __restrict__ ei)
{
    int e = blockIdx.x * blockDim.x + threadIdx.x;
    if (e >= NE) return;
    int s = ei[e], d = ei[NE + e];
    atomicAdd(&g_den[d], expf(lrelu(g_as[s] + g_ad[d]) - g_emax[d]));
}

// ---------------- self-loop message initializes g_hA -------------------------
__global__ void node_self_kernel()
{
    int idx  = blockIdx.x * blockDim.x + threadIdx.x;
    int n    = idx >> 5;
    int lane = idx & 31;
    if (n >= NN) return;
    float coef = expf(lrelu(g_as[n] + g_ad[n]) - g_emax[n]) / (g_den[n] + 1e-16f);
    float4 h = ((const float4*)(g_h2 + (size_t)n * FD))[lane];
    float4 o = make_float4(coef * h.x, coef * h.y, coef * h.z, coef * h.w);
    ((float4*)(g_hA + (size_t)n * FD))[lane] = o;
}

// ---------------- edge scatter: warp per edge, vector red.add ----------------
__global__ void edge_scatter_kernel(const int* __restrict__ ei)
{
    int idx  = blockIdx.x * blockDim.x + threadIdx.x;
    int e    = idx >> 5;
    int lane = idx & 31;
    if (e >= NE) return;
    int s = 0, d = 0;
    float coef = 0.f;
    if (lane == 0) {
        s = ei[e];
        d = ei[NE + e];
        coef = expf(lrelu(g_as[s] + g_ad[d]) - g_emax[d]) / (g_den[d] + 1e-16f);
    }
    s    = __shfl_sync(0xffffffffu, s, 0);
    d    = __shfl_sync(0xffffffffu, d, 0);
    coef = __shfl_sync(0xffffffffu, coef, 0);

    float4 h = ((const float4*)(g_h2 + (size_t)s * FD))[lane];
    float* p = g_hA + (size_t)d * FD + lane * 4;
    asm volatile("red.global.add.v4.f32 [%0], {%1, %2, %3, %4};"
                 :: "l"(p), "f"(coef * h.x), "f"(coef * h.y),
                    "f"(coef * h.z), "f"(coef * h.w)
                 : "memory");
}

// ---------------- pooling ----------------------------------------------------
__global__ void zero_pool_kernel()
{
    int i = blockIdx.x * blockDim.x + threadIdx.x;
    if (i < NG * FD) g_pool[i] = 0.f;
    if (i < NG)      g_cnt[i]  = 0.f;
}

// batch is sorted -> accumulate contiguous runs in registers, flush rarely
__global__ __launch_bounds__(128) void pool_kernel(const int* __restrict__ batch,
                                                   const float* __restrict__ bias)
{
    int f  = threadIdx.x;
    int n0 = blockIdx.x * 64;
    int n1 = min(n0 + 64, NN);
    float acc = 0.f, c = 0.f;
    int cur = batch[n0];
    for (int n = n0; n < n1; n++) {
        int g = batch[n];
        if (g != cur) {
            atomicAdd(&g_pool[cur * FD + f], acc);
            if (f == 0) atomicAdd(&g_cnt[cur], c);
            acc = 0.f; c = 0.f; cur = g;
        }
        float v = g_hA[(size_t)n * FD + f] + bias[f];
        acc += fmaxf(v, 0.f);
        c += 1.f;
    }
    atomicAdd(&g_pool[cur * FD + f], acc);
    if (f == 0) atomicAdd(&g_cnt[cur], c);
}

__global__ void final_kernel(const float* __restrict__ W1,
                             const float* __restrict__ b1,
                             float* __restrict__ out)
{
    int g = blockIdx.x;
    int c = threadIdx.x;
    if (c >= 10) return;
    float cc = fmaxf(g_cnt[g], 1.f);
    float s = 0.f;
    #pragma unroll 4
    for (int f = 0; f < FD; f++) s += g_pool[g * FD + f] * W1[f * 10 + c];
    out[g * 10 + c] = s / cc + b1[c];
}

// ---------------- launch ------------------------------------------------------
extern "C" void kernel_launch(void* const* d_in, const int* in_sizes, int n_in,
                              void* d_out, int out_size)
{
    const float* x     = (const float*)d_in[0];
    const int*   ei    = (const int*)d_in[1];
    /* d_in[2] edge_attr: unused by reference */
    const int*   batch = (const int*)d_in[3];
    const float* W0    = (const float*)d_in[4];
    const float* b0    = (const float*)d_in[5];
    const float* Wc    = (const float*)d_in[6];
    const float* asr   = (const float*)d_in[7];
    const float* adt   = (const float*)d_in[8];
    const float* bc    = (const float*)d_in[9];
    const float* W1    = (const float*)d_in[10];
    const float* b1    = (const float*)d_in[11];
    float*       out   = (float*)d_out;

    float *p_hA, *p_h2;
    cudaGetSymbolAddress((void**)&p_hA, g_hA);
    cudaGetSymbolAddress((void**)&p_h2, g_h2);

    const int gemm_blocks = (NN + 63) / 64;
    const int nwb = (NN * 32 + 255) / 256;   // warp-per-node
    const int nnb = (NN + 255) / 256;        // thread-per-node
    const int neb = (NE + 255) / 256;        // thread-per-edge
    const int esb = (NE * 32 + 255) / 256;   // warp-per-edge

    // h0 = relu(x @ W0 + b0)
    gemm_kernel<<<gemm_blocks, 128>>>(x, W0, nullptr, 0, b0, 1, p_hA, NN);

    for (int l = 0; l < 3; l++) {
        const float* in_bias = (l == 0) ? nullptr : (bc + (size_t)(l - 1) * FD);
        int in_relu = (l == 0) ? 0 : 1;
        // h2 = f(hA) @ Wc[l]
        gemm_kernel<<<gemm_blocks, 128>>>(p_hA, Wc + (size_t)l * FD * FD,
                                          in_bias, in_relu, nullptr, 0, p_h2, NN);
        node_alpha_kernel<<<nwb, 256>>>(asr + (size_t)l * FD, adt + (size_t)l * FD);
        edge_max_kernel<<<neb, 256>>>(ei);
        node_denom_kernel<<<nnb, 256>>>();
        edge_sum_kernel<<<neb, 256>>>(ei);
        node_self_kernel<<<nwb, 256>>>();
        edge_scatter_kernel<<<esb, 256>>>(ei);
    }

    zero_pool_kernel<<<(NG * FD + 255) / 256, 256>>>();
    pool_kernel<<<(NN + 63) / 64, 128>>>(batch, bc + 2 * FD);
    final_kernel<<<NG, 32>>>(W1, b1, out);
}

// round 15
// speedup vs baseline: 1.0057x; 1.0057x over previous
#include <cuda_runtime.h>

#define NN 50000
#define NE 800000
#define NG 64
#define FD 128
#define NEG_SLOPE 0.2f

// ---------------- device scratch (allocation-free rule: __device__ globals) ---
__device__ float g_hA[(size_t)NN * FD];   // current features / aggregation target
__device__ float g_h2[(size_t)NN * FD];   // transformed features h @ Wc
__device__ float g_as[NN];                // alpha_src per node
__device__ float g_ad[NN];                // alpha_dst per node
__device__ float g_emax[NN];              // segment max
__device__ float g_den[NN];               // segment softmax denominator
__device__ float g_pool[NG * FD];         // pooled sums
__device__ float g_cnt[NG];               // node counts per graph

__device__ __forceinline__ float lrelu(float x) { return x > 0.f ? x : NEG_SLOPE * x; }

__device__ __forceinline__ void atomicMaxF(float* addr, float val) {
    // monotone-toward-max under both ops; correct for mixed signs
    if (val >= 0.f) atomicMax((int*)addr, __float_as_int(val));
    else            atomicMin((unsigned int*)addr, __float_as_uint(val));
}

// ---------------- GEMM: C[nrows,128] = f(A)[nrows,128] @ B[128,128] ----------
// f(A) = optional (A + in_bias) then relu (fuses the post-aggregation bias+relu
// of the previous GAT layer into the next layer's GEMM load).
__global__ __launch_bounds__(128) void gemm_kernel(
    const float* __restrict__ A, const float* __restrict__ B,
    const float* __restrict__ in_bias, int in_relu,
    const float* __restrict__ out_bias, int out_relu,
    float* __restrict__ C, int nrows)
{
    __shared__ __align__(16) float As[64][33];
    __shared__ __align__(16) float Bs[32][132];

    const int tid  = threadIdx.x;
    const int row0 = blockIdx.x * 64;
    const int tr   = tid >> 4;   // 0..7  -> rows tr*8 .. tr*8+7
    const int tc   = tid & 15;   // 0..15 -> cols tc*8 .. tc*8+7

    float acc[8][8] = {};

    for (int kt = 0; kt < 128; kt += 32) {
        // load A tile 64x32 (with optional input transform)
        #pragma unroll
        for (int i = tid; i < 64 * 32; i += 128) {
            int rr = i >> 5, kk = i & 31;
            int row = row0 + rr;
            float v = 0.f;
            if (row < nrows) {
                v = A[(size_t)row * FD + kt + kk];
                if (in_bias) v += in_bias[kt + kk];
                if (in_relu) v = fmaxf(v, 0.f);
            }
            As[rr][kk] = v;
        }
        // load B tile 32x128 (coalesced)
        #pragma unroll
        for (int i = tid; i < 32 * 128; i += 128) {
            int kk = i >> 7, cc = i & 127;
            Bs[kk][cc] = B[(size_t)(kt + kk) * FD + cc];
        }
        __syncthreads();

        #pragma unroll
        for (int k = 0; k < 32; k++) {
            float a[8];
            #pragma unroll
            for (int i = 0; i < 8; i++) a[i] = As[tr * 8 + i][k];
            float4 b0 = *(const float4*)&Bs[k][tc * 8];
            float4 b1 = *(const float4*)&Bs[k][tc * 8 + 4];
            float b[8] = {b0.x, b0.y, b0.z, b0.w, b1.x, b1.y, b1.z, b1.w};
            #pragma unroll
            for (int i = 0; i < 8; i++)
                #pragma unroll
                for (int j = 0; j < 8; j++)
                    acc[i][j] += a[i] * b[j];
        }
        __syncthreads();
    }

    #pragma unroll
    for (int i = 0; i < 8; i++) {
        int row = row0 + tr * 8 + i;
        if (row >= nrows) break;
        #pragma unroll
        for (int j = 0; j < 8; j++) {
            int c = tc * 8 + j;
            float v = acc[i][j];
            if (out_bias) v += out_bias[c];
            if (out_relu) v = fmaxf(v, 0.f);
            C[(size_t)row * FD + c] = v;
        }
    }
}

// ---------------- per-node alpha dots + self-loop init of e_max --------------
__global__ void node_alpha_kernel(const float* __restrict__ asrc,
                                  const float* __restrict__ adst)
{
    int idx  = blockIdx.x * blockDim.x + threadIdx.x;
    int n    = idx >> 5;
    int lane = idx & 31;
    if (n >= NN) return;
    float4 h = ((const float4*)(g_h2 + (size_t)n * FD))[lane];
    float4 s = ((const float4*)asrc)[lane];
    float4 d = ((const float4*)adst)[lane];
    float ss = h.x * s.x + h.y * s.y + h.z * s.z + h.w * s.w;
    float dd = h.x * d.x + h.y * d.y + h.z * d.z + h.w * d.w;
    #pragma unroll
    for (int o = 16; o > 0; o >>= 1) {
        ss += __shfl_down_sync(0xffffffffu, ss, o);
        dd += __shfl_down_sync(0xffffffffu, dd, o);
    }
    if (lane == 0) {
        g_as[n]   = ss;
        g_ad[n]   = dd;
        g_emax[n] = lrelu(ss + dd);   // self-loop edge initializes segment max
    }
}

__global__ void edge_max_kernel(const int* __restrict__ ei)
{
    int e = blockIdx.x * blockDim.x + threadIdx.x;
    if (e >= NE) return;
    int s = ei[e], d = ei[NE + e];
    atomicMaxF(&g_emax[d], lrelu(g_as[s] + g_ad[d]));
}

__global__ void node_denom_kernel()
{
    int n = blockIdx.x * blockDim.x + threadIdx.x;
    if (n >= NN) return;
    // self-loop contribution initializes the denominator
    g_den[n] = expf(lrelu(g_as[n] + g_ad[n]) - g_emax[n]);
}

__global__ void edge_sum_kernel(const int* __restrict__ ei)
{
    int e = blockIdx.x * blockDim.x + threadIdx.x;
    if (e >= NE) return;
    int s = ei[e], d = ei[NE + e];
    atomicAdd(&g_den[d], expf(lrelu(g_as[s] + g_ad[d]) - g_emax[d]));
}

// ---------------- self-loop message initializes g_hA -------------------------
__global__ void node_self_kernel()
{
    int idx  = blockIdx.x * blockDim.x + threadIdx.x;
    int n    = idx >> 5;
    int lane = idx & 31;
    if (n >= NN) return;
    float coef = expf(lrelu(g_as[n] + g_ad[n]) - g_emax[n]) / (g_den[n] + 1e-16f);
    float4 h = ((const float4*)(g_h2 + (size_t)n * FD))[lane];
    float4 o = make_float4(coef * h.x, coef * h.y, coef * h.z, coef * h.w);
    ((float4*)(g_hA + (size_t)n * FD))[lane] = o;
}

// ---------------- edge scatter: warp per edge, vector red.add ----------------
__global__ void edge_scatter_kernel(const int* __restrict__ ei)
{
    int idx  = blockIdx.x * blockDim.x + threadIdx.x;
    int e    = idx >> 5;
    int lane = idx & 31;
    if (e >= NE) return;
    int s = 0, d = 0;
    float coef = 0.f;
    if (lane == 0) {
        s = ei[e];
        d = ei[NE + e];
        coef = expf(lrelu(g_as[s] + g_ad[d]) - g_emax[d]) / (g_den[d] + 1e-16f);
    }
    s    = __shfl_sync(0xffffffffu, s, 0);
    d    = __shfl_sync(0xffffffffu, d, 0);
    coef = __shfl_sync(0xffffffffu, coef, 0);

    float4 h = ((const float4*)(g_h2 + (size_t)s * FD))[lane];
    float* p = g_hA + (size_t)d * FD + lane * 4;
    asm volatile("red.global.add.v4.f32 [%0], {%1, %2, %3, %4};"
                 :: "l"(p), "f"(coef * h.x), "f"(coef * h.y),
                    "f"(coef * h.z), "f"(coef * h.w)
                 : "memory");
}

// ---------------- pooling ----------------------------------------------------
__global__ void zero_pool_kernel()
{
    int i = blockIdx.x * blockDim.x + threadIdx.x;
    if (i < NG * FD) g_pool[i] = 0.f;
    if (i < NG)      g_cnt[i]  = 0.f;
}

// batch is sorted -> accumulate contiguous runs in registers, flush rarely
__global__ __launch_bounds__(128) void pool_kernel(const int* __restrict__ batch,
                                                   const float* __restrict__ bias)
{
    int f  = threadIdx.x;
    int n0 = blockIdx.x * 64;
    int n1 = min(n0 + 64, NN);
    float acc = 0.f, c = 0.f;
    int cur = batch[n0];
    for (int n = n0; n < n1; n++) {
        int g = batch[n];
        if (g != cur) {
            atomicAdd(&g_pool[cur * FD + f], acc);
            if (f == 0) atomicAdd(&g_cnt[cur], c);
            acc = 0.f; c = 0.f; cur = g;
        }
        float v = g_hA[(size_t)n * FD + f] + bias[f];
        acc += fmaxf(v, 0.f);
        c += 1.f;
    }
    atomicAdd(&g_pool[cur * FD + f], acc);
    if (f == 0) atomicAdd(&g_cnt[cur], c);
}

__global__ void final_kernel(const float* __restrict__ W1,
                             const float* __restrict__ b1,
                             float* __restrict__ out)
{
    int g = blockIdx.x;
    int c = threadIdx.x;
    if (c >= 10) return;
    float cc = fmaxf(g_cnt[g], 1.f);
    float s = 0.f;
    #pragma unroll 4
    for (int f = 0; f < FD; f++) s += g_pool[g * FD + f] * W1[f * 10 + c];
    out[g * 10 + c] = s / cc + b1[c];
}

// ---------------- launch ------------------------------------------------------
extern "C" void kernel_launch(void* const* d_in, const int* in_sizes, int n_in,
                              void* d_out, int out_size)
{
    const float* x     = (const float*)d_in[0];
    const int*   ei    = (const int*)d_in[1];
    /* d_in[2] edge_attr: unused by reference */
    const int*   batch = (const int*)d_in[3];
    const float* W0    = (const float*)d_in[4];
    const float* b0    = (const float*)d_in[5];
    const float* Wc    = (const float*)d_in[6];
    const float* asr   = (const float*)d_in[7];
    const float* adt   = (const float*)d_in[8];
    const float* bc    = (const float*)d_in[9];
    const float* W1    = (const float*)d_in[10];
    const float* b1    = (const float*)d_in[11];
    float*       out   = (float*)d_out;

    float *p_hA, *p_h2;
    cudaGetSymbolAddress((void**)&p_hA, g_hA);
    cudaGetSymbolAddress((void**)&p_h2, g_h2);

    const int gemm_blocks = (NN + 63) / 64;
    const int nwb = (NN * 32 + 255) / 256;   // warp-per-node
    const int nnb = (NN + 255) / 256;        // thread-per-node
    const int neb = (NE + 255) / 256;        // thread-per-edge
    const int esb = (NE * 32 + 255) / 256;   // warp-per-edge

    // h0 = relu(x @ W0 + b0)
    gemm_kernel<<<gemm_blocks, 128>>>(x, W0, nullptr, 0, b0, 1, p_hA, NN);

    for (int l = 0; l < 3; l++) {
        const float* in_bias = (l == 0) ? nullptr : (bc + (size_t)(l - 1) * FD);
        int in_relu = (l == 0) ? 0 : 1;
        // h2 = f(hA) @ Wc[l]
        gemm_kernel<<<gemm_blocks, 128>>>(p_hA, Wc + (size_t)l * FD * FD,
                                          in_bias, in_relu, nullptr, 0, p_h2, NN);
        node_alpha_kernel<<<nwb, 256>>>(asr + (size_t)l * FD, adt + (size_t)l * FD);
        edge_max_kernel<<<neb, 256>>>(ei);
        node_denom_kernel<<<nnb, 256>>>();
        edge_sum_kernel<<<neb, 256>>>(ei);
        node_self_kernel<<<nwb, 256>>>();
        edge_scatter_kernel<<<esb, 256>>>(ei);
    }

    zero_pool_kernel<<<(NG * FD + 255) / 256, 256>>>();
    pool_kernel<<<(NN + 63) / 64, 128>>>(batch, bc + 2 * FD);
    final_kernel<<<NG, 32>>>(W1, b1, out);
}

// round 16
// speedup vs baseline: 1.0086x; 1.0029x over previous
#include <cuda_runtime.h>

#define NN 50000
#define NE 800000
#define NG 64
#define FD 128
#define NEG_SLOPE 0.2f

// ---------------- device scratch (allocation-free rule: __device__ globals) ---
__device__ float g_hA[(size_t)NN * FD];   // current features / aggregation target
__device__ float g_h2[(size_t)NN * FD];   // transformed features h @ Wc
__device__ float g_as[NN];                // alpha_src per node
__device__ float g_ad[NN];                // alpha_dst per node
__device__ float g_emax[NN];              // segment max
__device__ float g_den[NN];               // segment softmax denominator
__device__ float g_pool[NG * FD];         // pooled sums
__device__ float g_cnt[NG];               // node counts per graph

__device__ __forceinline__ float lrelu(float x) { return x > 0.f ? x : NEG_SLOPE * x; }

__device__ __forceinline__ void atomicMaxF(float* addr, float val) {
    // monotone-toward-max under both ops; correct for mixed signs
    if (val >= 0.f) atomicMax((int*)addr, __float_as_int(val));
    else            atomicMin((unsigned int*)addr, __float_as_uint(val));
}

// ---------------- GEMM: C[nrows,128] = f(A)[nrows,128] @ B[128,128] ----------
// f(A) = optional (A + in_bias) then relu (fuses the post-aggregation bias+relu
// of the previous GAT layer into the next layer's GEMM load).
__global__ __launch_bounds__(128) void gemm_kernel(
    const float* __restrict__ A, const float* __restrict__ B,
    const float* __restrict__ in_bias, int in_relu,
    const float* __restrict__ out_bias, int out_relu,
    float* __restrict__ C, int nrows)
{
    __shared__ __align__(16) float As[64][33];
    __shared__ __align__(16) float Bs[32][132];

    const int tid  = threadIdx.x;
    const int row0 = blockIdx.x * 64;
    const int tr   = tid >> 4;   // 0..7  -> rows tr*8 .. tr*8+7
    const int tc   = tid & 15;   // 0..15 -> cols tc*8 .. tc*8+7

    float acc[8][8] = {};

    for (int kt = 0; kt < 128; kt += 32) {
        // load A tile 64x32 (with optional input transform)
        #pragma unroll
        for (int i = tid; i < 64 * 32; i += 128) {
            int rr = i >> 5, kk = i & 31;
            int row = row0 + rr;
            float v = 0.f;
            if (row < nrows) {
                v = A[(size_t)row * FD + kt + kk];
                if (in_bias) v += in_bias[kt + kk];
                if (in_relu) v = fmaxf(v, 0.f);
            }
            As[rr][kk] = v;
        }
        // load B tile 32x128 (coalesced)
        #pragma unroll
        for (int i = tid; i < 32 * 128; i += 128) {
            int kk = i >> 7, cc = i & 127;
            Bs[kk][cc] = B[(size_t)(kt + kk) * FD + cc];
        }
        __syncthreads();

        #pragma unroll
        for (int k = 0; k < 32; k++) {
            float a[8];
            #pragma unroll
            for (int i = 0; i < 8; i++) a[i] = As[tr * 8 + i][k];
            float4 b0 = *(const float4*)&Bs[k][tc * 8];
            float4 b1 = *(const float4*)&Bs[k][tc * 8 + 4];
            float b[8] = {b0.x, b0.y, b0.z, b0.w, b1.x, b1.y, b1.z, b1.w};
            #pragma unroll
            for (int i = 0; i < 8; i++)
                #pragma unroll
                for (int j = 0; j < 8; j++)
                    acc[i][j] += a[i] * b[j];
        }
        __syncthreads();
    }

    #pragma unroll
    for (int i = 0; i < 8; i++) {
        int row = row0 + tr * 8 + i;
        if (row >= nrows) break;
        #pragma unroll
        for (int j = 0; j < 8; j++) {
            int c = tc * 8 + j;
            float v = acc[i][j];
            if (out_bias) v += out_bias[c];
            if (out_relu) v = fmaxf(v, 0.f);
            C[(size_t)row * FD + c] = v;
        }
    }
}

// ---------------- per-node alpha dots + self-loop init of e_max --------------
__global__ void node_alpha_kernel(const float* __restrict__ asrc,
                                  const float* __restrict__ adst)
{
    int idx  = blockIdx.x * blockDim.x + threadIdx.x;
    int n    = idx >> 5;
    int lane = idx & 31;
    if (n >= NN) return;
    float4 h = ((const float4*)(g_h2 + (size_t)n * FD))[lane];
    float4 s = ((const float4*)asrc)[lane];
    float4 d = ((const float4*)adst)[lane];
    float ss = h.x * s.x + h.y * s.y + h.z * s.z + h.w * s.w;
    float dd = h.x * d.x + h.y * d.y + h.z * d.z + h.w * d.w;
    #pragma unroll
    for (int o = 16; o > 0; o >>= 1) {
        ss += __shfl_down_sync(0xffffffffu, ss, o);
        dd += __shfl_down_sync(0xffffffffu, dd, o);
    }
    if (lane == 0) {
        g_as[n]   = ss;
        g_ad[n]   = dd;
        g_emax[n] = lrelu(ss + dd);   // self-loop edge initializes segment max
    }
}

__global__ void edge_max_kernel(const int* __restrict__ ei)
{
    int e = blockIdx.x * blockDim.x + threadIdx.x;
    if (e >= NE) return;
    int s = ei[e], d = ei[NE + e];
    atomicMaxF(&g_emax[d], lrelu(g_as[s] + g_ad[d]));
}

__global__ void node_denom_kernel()
{
    int n = blockIdx.x * blockDim.x + threadIdx.x;
    if (n >= NN) return;
    // self-loop contribution initializes the denominator
    g_den[n] = expf(lrelu(g_as[n] + g_ad[n]) - g_emax[n]);
}

__global__ void edge_sum_kernel(const int* __restrict__ ei)
{
    int e = blockIdx.x * blockDim.x + threadIdx.x;
    if (e >= NE) return;
    int s = ei[e], d = ei[NE + e];
    atomicAdd(&g_den[d], expf(lrelu(g_as[s] + g_ad[d]) - g_emax[d]));
}

// ---------------- self-loop message initializes g_hA -------------------------
__global__ void node_self_kernel()
{
    int idx  = blockIdx.x * blockDim.x + threadIdx.x;
    int n    = idx >> 5;
    int lane = idx & 31;
    if (n >= NN) return;
    float coef = expf(lrelu(g_as[n] + g_ad[n]) - g_emax[n]) / (g_den[n] + 1e-16f);
    float4 h = ((const float4*)(g_h2 + (size_t)n * FD))[lane];
    float4 o = make_float4(coef * h.x, coef * h.y, coef * h.z, coef * h.w);
    ((float4*)(g_hA + (size_t)n * FD))[lane] = o;
}

// ---------------- edge scatter: warp per edge, vector red.add ----------------
__global__ void edge_scatter_kernel(const int* __restrict__ ei)
{
    int idx  = blockIdx.x * blockDim.x + threadIdx.x;
    int e    = idx >> 5;
    int lane = idx & 31;
    if (e >= NE) return;
    int s = 0, d = 0;
    float coef = 0.f;
    if (lane == 0) {
        s = ei[e];
        d = ei[NE + e];
        coef = expf(lrelu(g_as[s] + g_ad[d]) - g_emax[d]) / (g_den[d] + 1e-16f);
    }
    s    = __shfl_sync(0xffffffffu, s, 0);
    d    = __shfl_sync(0xffffffffu, d, 0);
    coef = __shfl_sync(0xffffffffu, coef, 0);

    float4 h = ((const float4*)(g_h2 + (size_t)s * FD))[lane];
    float* p = g_hA + (size_t)d * FD + lane * 4;
    asm volatile("red.global.add.v4.f32 [%0], {%1, %2, %3, %4};"
                 :: "l"(p), "f"(coef * h.x), "f"(coef * h.y),
                    "f"(coef * h.z), "f"(coef * h.w)
                 : "memory");
}

// ---------------- pooling ----------------------------------------------------
__global__ void zero_pool_kernel()
{
    int i = blockIdx.x * blockDim.x + threadIdx.x;
    if (i < NG * FD) g_pool[i] = 0.f;
    if (i < NG)      g_cnt[i]  = 0.f;
}

// batch is sorted -> accumulate contiguous runs in registers, flush rarely
__global__ __launch_bounds__(128) void pool_kernel(const int* __restrict__ batch,
                                                   const float* __restrict__ bias)
{
    int f  = threadIdx.x;
    int n0 = blockIdx.x * 64;
    int n1 = min(n0 + 64, NN);
    float acc = 0.f, c = 0.f;
    int cur = batch[n0];
    for (int n = n0; n < n1; n++) {
        int g = batch[n];
        if (g != cur) {
            atomicAdd(&g_pool[cur * FD + f], acc);
            if (f == 0) atomicAdd(&g_cnt[cur], c);
            acc = 0.f; c = 0.f; cur = g;
        }
        float v = g_hA[(size_t)n * FD + f] + bias[f];
        acc += fmaxf(v, 0.f);
        c += 1.f;
    }
    atomicAdd(&g_pool[cur * FD + f], acc);
    if (f == 0) atomicAdd(&g_cnt[cur], c);
}

__global__ void final_kernel(const float* __restrict__ W1,
                             const float* __restrict__ b1,
                             float* __restrict__ out)
{
    int g = blockIdx.x;
    int c = threadIdx.x;
    if (c >= 10) return;
    float cc = fmaxf(g_cnt[g], 1.f);
    float s = 0.f;
    #pragma unroll 4
    for (int f = 0; f < FD; f++) s += g_pool[g * FD + f] * W1[f * 10 + c];
    out[g * 10 + c] = s / cc + b1[c];
}

// ---------------- launch ------------------------------------------------------
extern "C" void kernel_launch(void* const* d_in, const int* in_sizes, int n_in,
                              void* d_out, int out_size)
{
    const float* x     = (const float*)d_in[0];
    const int*   ei    = (const int*)d_in[1];
    /* d_in[2] edge_attr: unused by reference */
    const int*   batch = (const int*)d_in[3];
    const float* W0    = (const float*)d_in[4];
    const float* b0    = (const float*)d_in[5];
    const float* Wc    = (const float*)d_in[6];
    const float* asr   = (const float*)d_in[7];
    const float* adt   = (const float*)d_in[8];
    const float* bc    = (const float*)d_in[9];
    const float* W1    = (const float*)d_in[10];
    const float* b1    = (const float*)d_in[11];
    float*       out   = (float*)d_out;

    float *p_hA, *p_h2;
    cudaGetSymbolAddress((void**)&p_hA, g_hA);
    cudaGetSymbolAddress((void**)&p_h2, g_h2);

    const int gemm_blocks = (NN + 63) / 64;
    const int nwb = (NN * 32 + 255) / 256;   // warp-per-node
    const int nnb = (NN + 255) / 256;        // thread-per-node
    const int neb = (NE + 255) / 256;        // thread-per-edge
    const int esb = (NE * 32 + 255) / 256;   // warp-per-edge

    // h0 = relu(x @ W0 + b0)
    gemm_kernel<<<gemm_blocks, 128>>>(x, W0, nullptr, 0, b0, 1, p_hA, NN);

    for (int l = 0; l < 3; l++) {
        const float* in_bias = (l == 0) ? nullptr : (bc + (size_t)(l - 1) * FD);
        int in_relu = (l == 0) ? 0 : 1;
        // h2 = f(hA) @ Wc[l]
        gemm_kernel<<<gemm_blocks, 128>>>(p_hA, Wc + (size_t)l * FD * FD,
                                          in_bias, in_relu, nullptr, 0, p_h2, NN);
        node_alpha_kernel<<<nwb, 256>>>(asr + (size_t)l * FD, adt + (size_t)l * FD);
        edge_max_kernel<<<neb, 256>>>(ei);
        node_denom_kernel<<<nnb, 256>>>();
        edge_sum_kernel<<<neb, 256>>>(ei);
        node_self_kernel<<<nwb, 256>>>();
        edge_scatter_kernel<<<esb, 256>>>(ei);
    }

    zero_pool_kernel<<<(NG * FD + 255) / 256, 256>>>();
    pool_kernel<<<(NN + 63) / 64, 128>>>(batch, bc + 2 * FD);
    final_kernel<<<NG, 32>>>(W1, b1, out);
}